// round 4
// baseline (speedup 1.0000x reference)
#include <cuda_runtime.h>

// LIF_13984413516471  — B=128, S=128, H=128, K=8.
// s += x; spike = s > th[k]; out = spike ? s : 0; s -= out — serial over
// (i, j, k) per batch. Output: outs[b][i][k][j], spikes[b][i][k][j].
//
// A: per-chunk (one i-row = 1024 substeps) spec sim from s=0; smem-staged
//    coalesced output; records spec end state.
// B: PARALLEL verify+patch: candidate s_in = spec_state[chunk-1]; dual resim
//    (spec vs candidate-true), patch differing entries, early exit at first
//    co-spike (trajectories bitwise-identical after). ok[c] = end==spec end.
// D: per-batch O(1)-per-chunk validity walk; all-ok fast exit. Off-spec
//    chunks (rare) get an exact full rewrite resim.

#define BB 128
#define SS 128
#define HH 128
#define KK 8
#define NCHUNK (BB * SS)      // 16384
#define CPW 4
#define WPB 8
#define QJ 32
#define NQ (HH / QJ)

__device__ float g_spec_state[NCHUNK];
__device__ float g_end[NCHUNK];          // candidate-sim end (when no merge)
__device__ unsigned char g_ok[NCHUNK];   // candidate-sim end == spec end?

// ---------------------------------------------------------------- kernel A
__global__ __launch_bounds__(256) void lif_spec_kernel(
    const float* __restrict__ x, const float* __restrict__ th,
    float* __restrict__ outs, float* __restrict__ spikes, int write_spikes)
{
    __shared__ float buf[WPB][CPW][KK][QJ + 1];

    const int w    = threadIdx.x >> 5;
    const int lane = threadIdx.x & 31;
    const int gw   = blockIdx.x * WPB + w;
    const int chunk0 = gw * CPW;

    float t[KK];
#pragma unroll
    for (int k = 0; k < KK; ++k) t[k] = __ldg(th + k);

    const bool active = lane < CPW;
    const float* __restrict__ xr =
        x + (size_t)(chunk0 + (active ? lane : 0)) * HH;
    float* bp = &buf[w][active ? lane : 0][0][0];

    float s = 0.0f;

    for (int q = 0; q < NQ; ++q) {
        if (active) {
#pragma unroll
            for (int g = 0; g < QJ / 4; ++g) {
                float4 xv = *reinterpret_cast<const float4*>(xr + q * QJ + g * 4);
                float xa[4] = {xv.x, xv.y, xv.z, xv.w};
#pragma unroll
                for (int jj = 0; jj < 4; ++jj) {
                    float xx = xa[jj];
                    int j = g * 4 + jj;
#pragma unroll
                    for (int k = 0; k < KK; ++k) {
                        s += xx;
                        bool sp = s > t[k];
                        bp[k * (QJ + 1) + j] = sp ? s : 0.0f;
                        s = sp ? 0.0f : s;
                    }
                }
            }
        }
        __syncwarp();
#pragma unroll
        for (int c = 0; c < CPW; ++c) {
            size_t base = (size_t)(chunk0 + c) * (KK * HH) + q * QJ + lane;
#pragma unroll
            for (int k = 0; k < KK; ++k) {
                float v = buf[w][c][k][lane];
                outs[base + k * HH] = v;
                if (write_spikes) spikes[base + k * HH] = v > 0.0f ? 1.0f : 0.0f;
            }
        }
        __syncwarp();
    }

    if (active) g_spec_state[chunk0 + lane] = s;
}

// ---------------------------------------------------------------- kernel B
__global__ __launch_bounds__(128) void lif_verify_kernel(
    const float* __restrict__ x, const float* __restrict__ th,
    float* __restrict__ outs, float* __restrict__ spikes, int write_spikes)
{
    int chunk = blockIdx.x * 128 + threadIdx.x;
    if (chunk >= NCHUNK) return;

    int i = chunk & (SS - 1);
    float sb = (i == 0) ? 0.0f : g_spec_state[chunk - 1];   // candidate s_in
    if (sb == 0.0f) { g_ok[chunk] = 1; return; }            // spec exact

    float t[KK];
#pragma unroll
    for (int k = 0; k < KK; ++k) t[k] = __ldg(th + k);

    const float4* __restrict__ xr4 =
        reinterpret_cast<const float4*>(x + (size_t)chunk * HH);
    float* orow = outs + (size_t)chunk * (KK * HH);
    float* srow = spikes + (size_t)chunk * (KK * HH);

    float sa = 0.0f;    // spec trajectory
    float4 cur = xr4[0];
    for (int g = 0; g < HH / 4; ++g) {
        float4 nxt = (g + 1 < HH / 4) ? xr4[g + 1] : cur;
        float xa[4] = {cur.x, cur.y, cur.z, cur.w};
#pragma unroll
        for (int jj = 0; jj < 4; ++jj) {
            float xx = xa[jj];
            int j = g * 4 + jj;
#pragma unroll
            for (int k = 0; k < KK; ++k) {
                sa += xx; sb += xx;
                bool spa = sa > t[k];
                bool spb = sb > t[k];
                int idx = k * HH + j;
                if (spa && spb) {
                    // co-spike: bitwise-identical afterward; patch value only
                    orow[idx] = sb;
                    g_ok[chunk] = 1;
                    return;
                }
                float ot = spb ? sb : 0.0f;
                float os = spa ? sa : 0.0f;
                if (ot != os) orow[idx] = ot;
                if (write_spikes && (spa != spb)) srow[idx] = spb ? 1.0f : 0.0f;
                sa = spa ? 0.0f : sa;
                sb = spb ? 0.0f : sb;
            }
        }
        cur = nxt;
    }
    // never merged: record candidate end; ok iff it coincides with spec end
    g_end[chunk] = sb;
    g_ok[chunk] = (sb == g_spec_state[chunk]) ? 1 : 0;
}

// ---------------------------------------------------------------- kernel D
__device__ void resim_full(const float* __restrict__ xrow,
                           const float* __restrict__ t, float& s,
                           float* __restrict__ orow, float* __restrict__ srow,
                           int write_spikes)
{
    const float4* xr4 = reinterpret_cast<const float4*>(xrow);
    for (int g = 0; g < HH / 4; ++g) {
        float4 xv = xr4[g];
        float xa[4] = {xv.x, xv.y, xv.z, xv.w};
#pragma unroll
        for (int jj = 0; jj < 4; ++jj) {
            float xx = xa[jj];
            int j = g * 4 + jj;
#pragma unroll
            for (int k = 0; k < KK; ++k) {
                s += xx;
                bool sp = s > t[k];
                float o = sp ? s : 0.0f;
                orow[k * HH + j] = o;
                if (write_spikes) srow[k * HH + j] = sp ? 1.0f : 0.0f;
                s = sp ? 0.0f : s;
            }
        }
    }
}

__global__ void lif_fix_kernel(
    const float* __restrict__ x, const float* __restrict__ th,
    float* __restrict__ outs, float* __restrict__ spikes, int write_spikes)
{
    if (threadIdx.x != 0) return;
    int b = blockIdx.x;
    int base = b * SS;

    // fast all-ok check: 128 flag bytes as 8 x uint4
    const uint4* okv = reinterpret_cast<const uint4*>(g_ok + base);
    unsigned int acc = 0x01010101u;
#pragma unroll
    for (int i = 0; i < 8; ++i) {
        uint4 v = okv[i];
        acc &= v.x & v.y & v.z & v.w;
    }
    if (acc == 0x01010101u) return;

    float t[KK];
#pragma unroll
    for (int k = 0; k < KK; ++k) t[k] = __ldg(th + k);

    float s = 0.0f;
    bool on_spec = true;   // true end of previous chunk == its spec end
    for (int i = 1; i < SS; ++i) {
        int c = base + i;
        if (on_spec) {
            if (g_ok[c]) continue;
            // candidate s_in was correct; B's patch of chunk c is valid,
            // but its true end diverges from spec: go off-spec.
            s = g_end[c];
            on_spec = false;
            continue;
        }
        // off-spec: s = true end of chunk c-1 (!= spec). Full exact rewrite.
        resim_full(x + (size_t)c * HH, t, s,
                   outs + (size_t)c * (KK * HH),
                   spikes + (size_t)c * (KK * HH), write_spikes);
        if (s == g_spec_state[c]) on_spec = true;
    }
}

extern "C" void kernel_launch(void* const* d_in, const int* in_sizes, int n_in,
                              void* d_out, int out_size) {
    const float* x  = (const float*)d_in[0];   // (B, S, H) f32
    const float* th = (const float*)d_in[1];   // (K,) f32
    float* outs = (float*)d_out;

    const long long N = (long long)BB * SS * KK * HH;   // 16777216
    int write_spikes = ((long long)out_size >= 2 * N) ? 1 : 0;
    float* spikes = outs + N;

    lif_spec_kernel<<<NCHUNK / (CPW * WPB), WPB * 32>>>(x, th, outs, spikes,
                                                        write_spikes);
    lif_verify_kernel<<<NCHUNK / 128, 128>>>(x, th, outs, spikes, write_spikes);
    lif_fix_kernel<<<BB, 32>>>(x, th, outs, spikes, write_spikes);
}